// round 5
// baseline (speedup 1.0000x reference)
#include <cuda_runtime.h>

#define FULL 0xffffffffu

struct C { float x, y; };

// ===================== compile-time GF(2) circuit algebra =====================
// Index bit b = 9 - wire. CNOT ring (applied sequentially w=0..9) is the linear
// forward map G over GF(2) on basis labels. We never permute the state; a gate
// at layer L on logical bit b becomes a butterfly with storage XOR-mask
// m = G^-L(e_b) and role selector v = row_b(G^L); readout uses rows of G^6.
constexpr int NB = 10;
struct LM { int row[NB]; };

__host__ __device__ constexpr int par(int v) { int p = 0; for (int k = 0; k < 16; k++) p ^= (v >> k) & 1; return p; }

__host__ __device__ constexpr LM mkI() { LM M{}; for (int j = 0; j < NB; j++) M.row[j] = 1 << j; return M; }
// G: b_j_new = XOR(b_j..b_9) for j<=8 ; b_9_new = XOR(b_0..b_8)
__host__ __device__ constexpr LM mkR() {
    LM M{};
    for (int j = 0; j < 9; j++) M.row[j] = 0x3FF & ~((1 << j) - 1);
    M.row[9] = 0x1FF;
    return M;
}
// G^-1: b_j = c_j ^ c_{j+1} (j<=7); b_8 = c_8^c_0^c_9; b_9 = c_0^c_9
__host__ __device__ constexpr LM mkRinv() {
    LM M{};
    for (int j = 0; j < 8; j++) M.row[j] = 3 << j;
    M.row[8] = 0x301; M.row[9] = 0x201;
    return M;
}
__host__ __device__ constexpr LM mul(LM A, LM B) {  // (A o B)(i) = A(B(i))
    LM Cm{};
    for (int j = 0; j < NB; j++) {
        int m = 0;
        for (int k = 0; k < NB; k++) if ((A.row[j] >> k) & 1) m ^= B.row[k];
        Cm.row[j] = m;
    }
    return Cm;
}
__host__ __device__ constexpr int applyLM(LM M, int x) {
    int o = 0;
    for (int j = 0; j < NB; j++) o |= par(M.row[j] & x) << j;
    return o;
}

struct Tables { int m[6][10]; int v[6][10]; int vr[10]; };

__host__ __device__ constexpr Tables mkTables() {
    Tables T{};
    LM R = mkR(), Ri = mkRinv();
    LM L = mkI(), Li = mkI();
    for (int l = 0; l < 6; l++) {
        for (int w = 0; w < 10; w++) {
            int b = 9 - w;
            T.m[l][w] = applyLM(Li, 1 << b);   // storage-space butterfly mask
            T.v[l][w] = L.row[b];              // role selector (parity row)
        }
        L = mul(R, L); Li = mul(Ri, Li);
    }
    for (int w = 0; w < 10; w++) T.vr[w] = L.row[9 - w];  // final readout rows (G^6)
    return T;
}
constexpr Tables TBL = mkTables();   // host-side / template-argument use only

__host__ __device__ constexpr bool chkInv() {
    LM P = mul(mkR(), mkRinv());
    for (int j = 0; j < NB; j++) if (P.row[j] != (1 << j)) return false;
    return true;
}
static_assert(chkInv(), "R inverse wrong");
__host__ __device__ constexpr bool chkMV() {
    Tables T = mkTables();
    for (int l = 0; l < 6; l++)
        for (int w = 0; w < 10; w++)
            if (par(T.m[l][w] & T.v[l][w]) != 1) return false;
    return true;
}
static_assert(chkMV(), "mask/selector inconsistent");

__host__ __device__ constexpr int hb(int m) { int h = 1; for (int k = 0; k < NB; k++) if ((m >> k) & 1) h = 1 << k; return h; }

// ===================== precomputed Rot matrices (weight-only, grid-uniform) ===
__device__ float4 g_U[60];  // per (layer,wire): {au.x, au.y, bu.x, bu.y} of SU(2) Rot

__global__ void prep_kernel(const float* __restrict__ weights) {
    int idx = threadIdx.x;
    if (idx >= 60) return;
    float phi = weights[3 * idx + 0];
    float th  = weights[3 * idx + 1];
    float om  = weights[3 * idx + 2];
    float st, ct, sa, ca, sb, cb;
    __sincosf(0.5f * th,         &st, &ct);
    __sincosf(0.5f * (phi + om), &sa, &ca);
    __sincosf(0.5f * (phi - om), &sb, &cb);
    // Rot = [[a, b], [-conj(b), conj(a)]],  a = e^{-i(phi+om)/2} cos(th/2), b = -e^{i(phi-om)/2} sin(th/2)
    g_U[idx] = make_float4(ca * ct, -sa * ct, -cb * st, -sb * st);
}

// ===================== gate application =====================
// SU(2) gate [[a,b],[-conj(b),conj(a)]] applied with laneP folded into (al,be):
// element with role pr=0: new = al*s + be*o
// element with role pr=1: new = conj(al)*s - conj(be)*o   (signs are free FFMA modifiers)
__device__ __forceinline__ C gf0(C al, C be, C s, C o) {
    C r;
    r.x = fmaf(al.x, s.x, fmaf(-al.y, s.y, fmaf(be.x, o.x, -be.y * o.y)));
    r.y = fmaf(al.x, s.y, fmaf( al.y, s.x, fmaf(be.x, o.y,  be.y * o.x)));
    return r;
}
__device__ __forceinline__ C gf1(C al, C be, C s, C o) {
    C r;
    r.x = fmaf(al.x, s.x, fmaf( al.y, s.y, fmaf(-be.x, o.x, -be.y * o.y)));
    r.y = fmaf(al.x, s.y, fmaf(-al.y, s.x, fmaf(-be.x, o.y,  be.y * o.x)));
    return r;
}

template<int M, int V>
__device__ __forceinline__ void gate(C (&amp)[32], C ga, C gb, int lane) {
    constexpr int MR = (M >> 5) & 31, ML = M & 31;
    constexpr int VR = (V >> 5) & 31, VL = V & 31;
    const int laneP = VL ? (__popc(lane & VL) & 1) : 0;
    C al, be;
    al.x = ga.x; al.y = laneP ? -ga.y : ga.y;
    be.x = laneP ? -gb.x : gb.x; be.y = gb.y;

    if constexpr (ML == 0) {
        // partners share a lane; parity(MR&VR)==1 guaranteed => roles opposite
        constexpr int H = hb(MR);
#pragma unroll
        for (int r = 0; r < 32; r++) {
            if (r & H) continue;
            const int r2 = r ^ MR;
            C s = amp[r], o = amp[r2];
            if (__popc(r & VR) & 1) { amp[r] = gf1(al, be, s, o); amp[r2] = gf0(al, be, o, s); }
            else                    { amp[r] = gf0(al, be, s, o); amp[r2] = gf1(al, be, o, s); }
        }
    } else if constexpr (MR == 0) {
#pragma unroll
        for (int r = 0; r < 32; r++) {
            C o;
            o.x = __shfl_xor_sync(FULL, amp[r].x, ML);
            o.y = __shfl_xor_sync(FULL, amp[r].y, ML);
            if (__popc(r & VR) & 1) amp[r] = gf1(al, be, amp[r], o);
            else                    amp[r] = gf0(al, be, amp[r], o);
        }
    } else {
        // Mixed mask: partner of (r,lane) is (r^MR, lane^ML). Roles of same-lane
        // elements r and r^MR are NOT necessarily opposite (only parity(m&v)==1
        // overall) — compute each element's role independently.
        constexpr int H = hb(MR);
#pragma unroll
        for (int r = 0; r < 32; r++) {
            if (r & H) continue;
            const int r2 = r ^ MR;
            C o1, o2;
            o1.x = __shfl_xor_sync(FULL, amp[r2].x, ML);
            o1.y = __shfl_xor_sync(FULL, amp[r2].y, ML);
            o2.x = __shfl_xor_sync(FULL, amp[r].x, ML);
            o2.y = __shfl_xor_sync(FULL, amp[r].y, ML);
            C n1 = (__popc(r  & VR) & 1) ? gf1(al, be, amp[r],  o1) : gf0(al, be, amp[r],  o1);
            C n2 = (__popc(r2 & VR) & 1) ? gf1(al, be, amp[r2], o2) : gf0(al, be, amp[r2], o2);
            amp[r] = n1; amp[r2] = n2;
        }
    }
}

// Build fused gate M = Rot * RY(y) * RX(x) in SU(2) form (a=ga, b=gb).
__device__ __forceinline__ void build(int gidx, float cX, float sX, float cY, float sY, C& ga, C& gb) {
    const float4 u = g_U[gidx];
    C au{u.x, u.y}, bu{u.z, u.w};
    C ag{cY * cX,  sY * sX};
    C bg{-sY * cX, -cY * sX};
    // ga = au*ag - bu*conj(bg) ; gb = au*bg + bu*conj(ag)
    ga.x = fmaf(au.x, ag.x, fmaf(-au.y, ag.y, fmaf(-bu.x, bg.x, -bu.y * bg.y)));
    ga.y = fmaf(au.x, ag.y, fmaf( au.y, ag.x, fmaf(-bu.y, bg.x,  bu.x * bg.y)));
    gb.x = fmaf(au.x, bg.x, fmaf(-au.y, bg.y, fmaf( bu.x, ag.x,  bu.y * ag.y)));
    gb.y = fmaf(au.x, bg.y, fmaf( au.y, bg.x, fmaf( bu.y, ag.x, -bu.x * ag.y)));
}

template<int L, int W>
__device__ __forceinline__ void gates(C (&amp)[32], float cx0, float sx0, float cx1, float sx1, int lane) {
    if constexpr (W < 10) {
        C ga, gb;
        if constexpr ((W & 1) == 0) build(L * 10 + W, cx0, sx0, cx1, sx1, ga, gb);  // RX(x0), RY(x1)
        else                        build(L * 10 + W, cx1, sx1, cx0, sx0, ga, gb);  // RX(x1), RY(x0)
        gate<TBL.m[L][W], TBL.v[L][W]>(amp, ga, gb, lane);
        gates<L, W + 1>(amp, cx0, sx0, cx1, sx1, lane);
    }
}

template<int L>
__device__ __forceinline__ void layers(C (&amp)[32], float cx0, float sx0, float cx1, float sx1, int lane) {
    if constexpr (L < 6) {
        gates<L, 0>(amp, cx0, sx0, cx1, sx1, lane);
        layers<L + 1>(amp, cx0, sx0, cx1, sx1, lane);
    }
}

// ===================== main kernel =====================
__global__ void __launch_bounds__(256)
qsim_kernel(const float* __restrict__ x,
            const float* __restrict__ post_W,
            const float* __restrict__ post_b,
            const float* __restrict__ readout,
            const float* __restrict__ bias,
            float* __restrict__ out,
            int batch)
{
    const int lane = threadIdx.x & 31;
    const int samp = (int)((blockIdx.x * blockDim.x + threadIdx.x) >> 5);
    if (samp >= batch) return;

    const float x0 = x[2 * samp + 0];
    const float x1 = x[2 * samp + 1];
    float sx0, cx0, sx1, cx1;
    __sincosf(0.5f * x0, &sx0, &cx0);
    __sincosf(0.5f * x1, &sx1, &cx1);

    C amp[32];
#pragma unroll
    for (int r = 0; r < 32; r++) { amp[r].x = 0.f; amp[r].y = 0.f; }
    if (lane == 0) amp[0].x = 1.0f;

    layers<0>(amp, cx0, sx0, cx1, sx1, lane);

    // Readout under residual permutation G^6: coef(i) = sum_w pw[w] * (-1)^<vr_w, i>
    constexpr Tables T = mkTables();

    float t[10];
#pragma unroll
    for (int w = 0; w < 10; w++) {
        const float pw = post_W[w];
        t[w] = (__popc(lane & (T.vr[w] & 31)) & 1) ? -pw : pw;
    }

    float acc = 0.f;
#pragma unroll
    for (int r = 0; r < 32; r++) {
        float coef = 0.f;
#pragma unroll
        for (int w = 0; w < 10; w++) {
            coef += (__popc(r & ((T.vr[w] >> 5) & 31)) & 1) ? -t[w] : t[w];
        }
        float prob = fmaf(amp[r].x, amp[r].x, amp[r].y * amp[r].y);
        acc = fmaf(prob, coef, acc);
    }

#pragma unroll
    for (int off = 16; off; off >>= 1)
        acc += __shfl_xor_sync(FULL, acc, off);

    if (lane == 0) {
        out[samp] = readout[0] * (acc + post_b[0]) + bias[0];
    }
}

extern "C" void kernel_launch(void* const* d_in, const int* in_sizes, int n_in,
                              void* d_out, int out_size)
{
    const float* x       = (const float*)d_in[0];
    const float* weights = (const float*)d_in[1];
    const float* post_W  = (const float*)d_in[2];
    const float* post_b  = (const float*)d_in[3];
    const float* readout = (const float*)d_in[4];
    const float* bias    = (const float*)d_in[5];
    float* out = (float*)d_out;

    const int batch = in_sizes[0] / 2;
    prep_kernel<<<1, 64>>>(weights);

    const int threads = 256;
    const int total_threads = batch * 32;
    const int blocks = (total_threads + threads - 1) / threads;
    qsim_kernel<<<blocks, threads>>>(x, post_W, post_b, readout, bias, out, batch);
}

// round 6
// speedup vs baseline: 1.7595x; 1.7595x over previous
#include <cuda_runtime.h>

#define FULL 0xffffffffu

struct C { float x, y; };

// ===================== precomputed Rot matrices (weight-only, grid-uniform) ===
__device__ float4 g_U[60];  // per (layer,wire): SU(2) Rot = [[a,b],[-conj(b),conj(a)]] -> {a.x,a.y,b.x,b.y}

__global__ void prep_kernel(const float* __restrict__ weights) {
    int idx = threadIdx.x;
    if (idx >= 60) return;
    float phi = weights[3 * idx + 0];
    float th  = weights[3 * idx + 1];
    float om  = weights[3 * idx + 2];
    float st, ct, sa, ca, sb, cb;
    __sincosf(0.5f * th,         &st, &ct);
    __sincosf(0.5f * (phi + om), &sa, &ca);
    __sincosf(0.5f * (phi - om), &sb, &cb);
    // a = e^{-i(phi+om)/2} cos(th/2),  b = -e^{i(phi-om)/2} sin(th/2)
    g_U[idx] = make_float4(ca * ct, -sa * ct, -cb * st, -sb * st);
}

// ===================== SU(2) gate application =====================
// Gate [[a,b],[-conj(b),conj(a)]]:
// role0: new = a*s + b*o          role1: new = conj(a)*s - conj(b)*o
__device__ __forceinline__ C gf0(C a, C b, C s, C o) {
    C r;
    r.x = fmaf(a.x, s.x, fmaf(-a.y, s.y, fmaf(b.x, o.x, -b.y * o.y)));
    r.y = fmaf(a.x, s.y, fmaf( a.y, s.x, fmaf(b.x, o.y,  b.y * o.x)));
    return r;
}
__device__ __forceinline__ C gf1(C a, C b, C s, C o) {
    C r;
    r.x = fmaf(a.x, s.x, fmaf( a.y, s.y, fmaf(-b.x, o.x, -b.y * o.y)));
    r.y = fmaf(a.x, s.y, fmaf(-a.y, s.x, fmaf(-b.x, o.y,  b.y * o.x)));
    return r;
}

// ===================== main kernel =====================
__global__ void __launch_bounds__(256, 2)
qsim_kernel(const float* __restrict__ x,
            const float* __restrict__ post_W,
            const float* __restrict__ post_b,
            const float* __restrict__ readout,
            const float* __restrict__ bias,
            float* __restrict__ out,
            int batch)
{
    const int lane = threadIdx.x & 31;
    const int samp = (int)((blockIdx.x * blockDim.x + threadIdx.x) >> 5);
    if (samp >= batch) return;

    const float x0 = x[2 * samp + 0];
    const float x1 = x[2 * samp + 1];
    float sx0, cx0, sx1, cx1;
    __sincosf(0.5f * x0, &sx0, &cx0);
    __sincosf(0.5f * x1, &sx1, &cx1);

    // Encoding product G = RY(y)*RX(x) in SU(2) form {ag, bg}.
    // ag = {cY*cX, sY*sX} is the SAME for even/odd wires; bg differs.
    const C ag   { cx1 * cx0,  sx1 * sx0 };
    const C bg_e { -sx1 * cx0, -cx1 * sx0 };  // even wires: RX(x0), RY(x1)
    const C bg_o { -sx0 * cx1, -cx0 * sx1 };  // odd  wires: RX(x1), RY(x0)

    // state: amplitude i = r*32 + lane; wire w <-> bit (9-w)
    C amp[32];
#pragma unroll
    for (int r = 0; r < 32; r++) { amp[r].x = 0.f; amp[r].y = 0.f; }
    if (lane == 0) amp[0].x = 1.0f;

    // Variable-source lanes for lane-lane CNOTs (ctrl bit cb, tgt bit tb):
    // src = (lane has cb) ? lane ^ (1<<tb) : lane
    const int src54 = (lane & 16) ? (lane ^ 8) : lane;  // w=5: cb=4, tb=3
    const int src43 = (lane &  8) ? (lane ^ 4) : lane;  // w=6: cb=3, tb=2
    const int src32 = (lane &  4) ? (lane ^ 2) : lane;  // w=7: cb=2, tb=1
    const int src21 = (lane &  2) ? (lane ^ 1) : lane;  // w=8: cb=1, tb=0
    const bool c0   = (lane & 1) != 0;                  // w=9 ctrl (lane bit 0)

#pragma unroll 1
    for (int layer = 0; layer < 6; layer++) {
        const float4* Ul = g_U + layer * 10;

        // ---- fused gates: M = Rot * (RY*RX) ----
#pragma unroll
        for (int w = 0; w < 10; w++) {
            const float4 u = Ul[w];
            const C au{u.x, u.y}, bu{u.z, u.w};
            const C bg = (w & 1) ? bg_o : bg_e;
            // ga = au*ag - bu*conj(bg) ; gb = au*bg + bu*conj(ag)
            C ga, gb;
            ga.x = fmaf(au.x, ag.x, fmaf(-au.y, ag.y, fmaf(-bu.x, bg.x, -bu.y * bg.y)));
            ga.y = fmaf(au.x, ag.y, fmaf( au.y, ag.x, fmaf(-bu.y, bg.x,  bu.x * bg.y)));
            gb.x = fmaf(au.x, bg.x, fmaf(-au.y, bg.y, fmaf( bu.x, ag.x,  bu.y * ag.y)));
            gb.y = fmaf(au.x, bg.y, fmaf( au.y, bg.x, fmaf( bu.y, ag.x, -bu.x * ag.y)));

            const int b = 9 - w;
            if (b >= 5) {
                const int s = 1 << (b - 5);
#pragma unroll
                for (int r = 0; r < 32; r++) {
                    if (r & s) continue;
                    C lo = amp[r], hi = amp[r | s];
                    amp[r]     = gf0(ga, gb, lo, hi);
                    amp[r | s] = gf1(ga, gb, hi, lo);
                }
            } else {
                const int m = 1 << b;
                const bool hi = (lane & m) != 0;
                C al, be;  // fold role into coefficients: hi -> conj(a), -conj(b)
                al.x = ga.x; al.y = hi ? -ga.y : ga.y;
                be.x = hi ? -gb.x : gb.x; be.y = gb.y;
#pragma unroll
                for (int r = 0; r < 32; r++) {
                    C o;
                    o.x = __shfl_xor_sync(FULL, amp[r].x, m);
                    o.y = __shfl_xor_sync(FULL, amp[r].y, m);
                    amp[r] = gf0(al, be, amp[r], o);
                }
            }
        }

        // ---- CNOT ring ----
        // w=0..3: ctrl/tgt both register bits -> compile-time register swaps (renamed away)
#pragma unroll
        for (int w = 0; w < 4; w++) {
            const int cs = 1 << (4 - w), ts = 1 << (3 - w);
#pragma unroll
            for (int r = 0; r < 32; r++) {
                if ((r & cs) && !(r & ts)) {
                    C t = amp[r]; amp[r] = amp[r | ts]; amp[r | ts] = t;
                }
            }
        }
        // w=4: ctrl reg bit0, tgt lane bit4 -> shuffle the odd-r registers
#pragma unroll
        for (int r = 0; r < 32; r++) {
            if (r & 1) {
                amp[r].x = __shfl_xor_sync(FULL, amp[r].x, 16);
                amp[r].y = __shfl_xor_sync(FULL, amp[r].y, 16);
            }
        }
        // w=5..8: both lane bits -> variable-source shuffle (no selects)
#pragma unroll
        for (int r = 0; r < 32; r++) {
            amp[r].x = __shfl_sync(FULL, amp[r].x, src54);
            amp[r].y = __shfl_sync(FULL, amp[r].y, src54);
        }
#pragma unroll
        for (int r = 0; r < 32; r++) {
            amp[r].x = __shfl_sync(FULL, amp[r].x, src43);
            amp[r].y = __shfl_sync(FULL, amp[r].y, src43);
        }
#pragma unroll
        for (int r = 0; r < 32; r++) {
            amp[r].x = __shfl_sync(FULL, amp[r].x, src32);
            amp[r].y = __shfl_sync(FULL, amp[r].y, src32);
        }
#pragma unroll
        for (int r = 0; r < 32; r++) {
            amp[r].x = __shfl_sync(FULL, amp[r].x, src21);
            amp[r].y = __shfl_sync(FULL, amp[r].y, src21);
        }
        // w=9: ctrl lane bit0, tgt reg bit4 -> lane-conditional register swap
#pragma unroll
        for (int r = 0; r < 16; r++) {
            C a = amp[r], d = amp[r + 16];
            amp[r].x      = c0 ? d.x : a.x;
            amp[r].y      = c0 ? d.y : a.y;
            amp[r + 16].x = c0 ? a.x : d.x;
            amp[r + 16].y = c0 ? a.y : d.y;
        }
    }

    // ---- readout: <Z_w> weighted by post_W ----
    float pw[10];
#pragma unroll
    for (int w = 0; w < 10; w++) pw[w] = post_W[w];

    float laneCoef = 0.f;
#pragma unroll
    for (int w = 5; w < 10; w++)
        laneCoef += ((lane >> (9 - w)) & 1) ? -pw[w] : pw[w];

    float acc = 0.f;
#pragma unroll
    for (int r = 0; r < 32; r++) {
        float coef = laneCoef;
#pragma unroll
        for (int w = 0; w < 5; w++)
            coef += ((r >> (4 - w)) & 1) ? -pw[w] : pw[w];
        float prob = fmaf(amp[r].x, amp[r].x, amp[r].y * amp[r].y);
        acc = fmaf(prob, coef, acc);
    }

#pragma unroll
    for (int off = 16; off; off >>= 1)
        acc += __shfl_xor_sync(FULL, acc, off);

    if (lane == 0)
        out[samp] = readout[0] * (acc + post_b[0]) + bias[0];
}

extern "C" void kernel_launch(void* const* d_in, const int* in_sizes, int n_in,
                              void* d_out, int out_size)
{
    const float* x       = (const float*)d_in[0];
    const float* weights = (const float*)d_in[1];
    const float* post_W  = (const float*)d_in[2];
    const float* post_b  = (const float*)d_in[3];
    const float* readout = (const float*)d_in[4];
    const float* bias    = (const float*)d_in[5];
    float* out = (float*)d_out;

    const int batch = in_sizes[0] / 2;
    prep_kernel<<<1, 64>>>(weights);

    const int threads = 256;
    const int total_threads = batch * 32;
    const int blocks = (total_threads + threads - 1) / threads;
    qsim_kernel<<<blocks, threads>>>(x, post_W, post_b, readout, bias, out, batch);
}

// round 7
// speedup vs baseline: 2.5721x; 1.4618x over previous
#include <cuda_runtime.h>

#define FULL 0xffffffffu

typedef unsigned long long u64;

struct C { float x, y; };

// ---------- f32x2 packed helpers (Blackwell packed fp32 pipe) ----------
__device__ __forceinline__ u64 PK(float lo, float hi) {
    u64 r;
    asm("mov.b64 %0, {%1, %2};" : "=l"(r)
        : "r"(__float_as_uint(lo)), "r"(__float_as_uint(hi)));
    return r;
}
__device__ __forceinline__ void UPK(u64 p, float& lo, float& hi) {
    unsigned a, b;
    asm("mov.b64 {%0, %1}, %2;" : "=r"(a), "=r"(b) : "l"(p));
    lo = __uint_as_float(a); hi = __uint_as_float(b);
}
__device__ __forceinline__ u64 F2(u64 a, u64 b, u64 c) {
    u64 d;
    asm("fma.rn.f32x2 %0, %1, %2, %3;" : "=l"(d) : "l"(a), "l"(b), "l"(c));
    return d;
}
__device__ __forceinline__ u64 M2(u64 a, u64 b) {
    u64 d;
    asm("mul.rn.f32x2 %0, %1, %2;" : "=l"(d) : "l"(a), "l"(b));
    return d;
}
__device__ __forceinline__ u64 B2(float v) { return PK(v, v); }
__device__ __forceinline__ u64 SW64(u64 p) { float l, h; UPK(p, l, h); return PK(h, l); }
__device__ __forceinline__ u64 SHX64(u64 p, int m) {
    float l, h; UPK(p, l, h);
    return PK(__shfl_xor_sync(FULL, l, m), __shfl_xor_sync(FULL, h, m));
}

// ---------- precomputed Rot matrices (weight-only, grid-uniform) ----------
__device__ float4 g_U[60];  // SU(2) Rot = [[a,b],[-conj(b),conj(a)]] -> {a.x,a.y,b.x,b.y}

__global__ void prep_kernel(const float* __restrict__ weights) {
    int idx = threadIdx.x;
    if (idx >= 60) return;
    float phi = weights[3 * idx + 0];
    float th  = weights[3 * idx + 1];
    float om  = weights[3 * idx + 2];
    float st, ct, sa, ca, sb, cb;
    __sincosf(0.5f * th,         &st, &ct);
    __sincosf(0.5f * (phi + om), &sa, &ca);
    __sincosf(0.5f * (phi - om), &sb, &cb);
    g_U[idx] = make_float4(ca * ct, -sa * ct, -cb * st, -sb * st);
}

// ===================== main kernel =====================
// State layout: amplitude index i = r*32 + lane, r = 2k + h.
// X[k] packs {Re(amp[2k]), Re(amp[2k+1])}; Y[k] the imaginary parts.
// Wire w <-> bit 9-w of i: w0..w3 -> pack bits 3..0, w4 -> packed half h,
// w5..w9 -> lane bits 4..0.
__global__ void __launch_bounds__(256, 2)
qsim_kernel(const float* __restrict__ x,
            const float* __restrict__ post_W,
            const float* __restrict__ post_b,
            const float* __restrict__ readout,
            const float* __restrict__ bias,
            float* __restrict__ out,
            int batch)
{
    const int lane = threadIdx.x & 31;
    const int samp = (int)((blockIdx.x * blockDim.x + threadIdx.x) >> 5);
    if (samp >= batch) return;

    const float x0 = x[2 * samp + 0];
    const float x1 = x[2 * samp + 1];
    float sx0, cx0, sx1, cx1;
    __sincosf(0.5f * x0, &sx0, &cx0);
    __sincosf(0.5f * x1, &sx1, &cx1);

    // Encoding product G = RY(y)*RX(x) in SU(2) form {ag, bg}; ag shared.
    const C ag   { cx1 * cx0,  sx1 * sx0 };
    const C bg_e { -sx1 * cx0, -cx1 * sx0 };  // even wires: RX(x0), RY(x1)
    const C bg_o { -sx0 * cx1, -cx0 * sx1 };  // odd  wires: RX(x1), RY(x0)

    u64 X[16], Y[16];
#pragma unroll
    for (int k = 0; k < 16; k++) { X[k] = 0ull; Y[k] = 0ull; }
    X[0] = PK(lane == 0 ? 1.0f : 0.0f, 0.0f);

    // Composed CNOT lane permutation g = f5∘f6∘f7∘f8 (innermost first):
    int gsrc = lane;
    gsrc = (gsrc & 2)  ? (gsrc ^ 1) : gsrc;  // w8: cb=1 tb=0
    gsrc = (gsrc & 4)  ? (gsrc ^ 2) : gsrc;  // w7: cb=2 tb=1
    gsrc = (gsrc & 8)  ? (gsrc ^ 4) : gsrc;  // w6: cb=3 tb=2
    gsrc = (gsrc & 16) ? (gsrc ^ 8) : gsrc;  // w5: cb=4 tb=3
    const int srcLo = gsrc;           // lo halves: pure perm
    const int srcHi = gsrc ^ 16;      // hi halves: w4 CNOT (xor16) then perm
    const bool c0 = (lane & 1) != 0;  // w9 ctrl

#pragma unroll 1
    for (int layer = 0; layer < 6; layer++) {
        const float4* Ul = g_U + layer * 10;

        // ---- fused gates: M = Rot * (RY*RX), SU(2) {ga, gb} ----
#pragma unroll
        for (int w = 0; w < 10; w++) {
            const float4 u = Ul[w];
            const C au{u.x, u.y}, bu{u.z, u.w};
            const C bg = (w & 1) ? bg_o : bg_e;
            C ga, gb;
            ga.x = fmaf(au.x, ag.x, fmaf(-au.y, ag.y, fmaf(-bu.x, bg.x, -bu.y * bg.y)));
            ga.y = fmaf(au.x, ag.y, fmaf( au.y, ag.x, fmaf(-bu.y, bg.x,  bu.x * bg.y)));
            gb.x = fmaf(au.x, bg.x, fmaf(-au.y, bg.y, fmaf( bu.x, ag.x,  bu.y * ag.y)));
            gb.y = fmaf(au.x, bg.y, fmaf( au.y, bg.x, fmaf( bu.y, ag.x, -bu.x * ag.y)));

            if (w <= 3) {
                // ---- inter-pack butterfly, pack-bit ks ----
                const int ks = 8 >> w;
                const u64 paxx = B2(ga.x), pnay = B2(-ga.y), ppay = B2(ga.y);
                const u64 pbxx = B2(gb.x), pnbx = B2(-gb.x);
                const u64 pnby = B2(-gb.y), ppby = B2(gb.y);
#pragma unroll
                for (int kl = 0; kl < 16; kl++) {
                    if (kl & ks) continue;
                    const int kh = kl | ks;
                    u64 Xl = X[kl], Yl = Y[kl], Xh = X[kh], Yh = Y[kh];
                    // new_lo = a*lo + b*hi ; new_hi = conj(a)*hi - conj(b)*lo
                    X[kl] = F2(paxx, Xl, F2(pnay, Yl, F2(pbxx, Xh, M2(pnby, Yh))));
                    Y[kl] = F2(paxx, Yl, F2(ppay, Xl, F2(pbxx, Yh, M2(ppby, Xh))));
                    X[kh] = F2(paxx, Xh, F2(ppay, Yh, F2(pnbx, Xl, M2(pnby, Yl))));
                    Y[kh] = F2(paxx, Yh, F2(pnay, Xh, F2(pnbx, Yl, M2(ppby, Xl))));
                }
            } else if (w == 4) {
                // ---- intra-pack butterfly (lo/hi halves of each pack) ----
                const u64 qaxx = B2(ga.x);
                const u64 qay  = PK(-ga.y,  ga.y);
                const u64 qay2 = PK( ga.y, -ga.y);
                const u64 qbx  = PK( gb.x, -gb.x);
                const u64 qnby = B2(-gb.y), qpby = B2(gb.y);
#pragma unroll
                for (int k = 0; k < 16; k++) {
                    u64 Xs = SW64(X[k]), Ys = SW64(Y[k]);
                    u64 nX = F2(qaxx, X[k], F2(qay,  Y[k], F2(qbx, Xs, M2(qnby, Ys))));
                    u64 nY = F2(qaxx, Y[k], F2(qay2, X[k], F2(qbx, Ys, M2(qpby, Xs))));
                    X[k] = nX; Y[k] = nY;
                }
            } else {
                // ---- lane-bit butterfly via shuffle; role folded into coeffs ----
                const int m = 1 << (9 - w);
                const bool hib = (lane & m) != 0;
                const float aly = hib ? -ga.y : ga.y;
                const float bex = hib ? -gb.x : gb.x;
                const u64 pA   = B2(ga.x);
                const u64 pAy  = B2(aly),  pnAy = B2(-aly);
                const u64 pBx  = B2(bex);
                const u64 pBy  = B2(gb.y), pnBy = B2(-gb.y);
#pragma unroll
                for (int k = 0; k < 16; k++) {
                    u64 OX = SHX64(X[k], m), OY = SHX64(Y[k], m);
                    u64 nX = F2(pA, X[k], F2(pnAy, Y[k], F2(pBx, OX, M2(pnBy, OY))));
                    u64 nY = F2(pA, Y[k], F2(pAy,  X[k], F2(pBx, OY, M2(pBy,  OX))));
                    X[k] = nX; Y[k] = nY;
                }
            }
        }

        // ---- CNOT ring ----
        // w0..w2: pure pack-index swaps (register renames, free)
#pragma unroll
        for (int k = 0; k < 16; k++) {
            if ((k & 8) && !(k & 4)) { u64 t = X[k]; X[k] = X[k ^ 4]; X[k ^ 4] = t;
                                       t = Y[k]; Y[k] = Y[k ^ 4]; Y[k ^ 4] = t; }
        }
#pragma unroll
        for (int k = 0; k < 16; k++) {
            if ((k & 4) && !(k & 2)) { u64 t = X[k]; X[k] = X[k ^ 2]; X[k ^ 2] = t;
                                       t = Y[k]; Y[k] = Y[k ^ 2]; Y[k ^ 2] = t; }
        }
#pragma unroll
        for (int k = 0; k < 16; k++) {
            if ((k & 2) && !(k & 1)) { u64 t = X[k]; X[k] = X[k ^ 1]; X[k ^ 1] = t;
                                       t = Y[k]; Y[k] = Y[k ^ 1]; Y[k ^ 1] = t; }
        }
        // w3 (odd packs swap halves) + w4 (hi halves xor16) + w5..w8 (lane perms)
        // all composed into one variable-source shuffle per 32-bit word.
#pragma unroll
        for (int k = 0; k < 16; k++) {
            float xl, xh, yl, yh;
            UPK(X[k], xl, xh); UPK(Y[k], yl, yh);
            float nxl, nxh, nyl, nyh;
            if (k & 1) {  // w3 swapped halves: lo reads old-hi, hi reads old-lo
                nxl = __shfl_sync(FULL, xh, srcLo); nxh = __shfl_sync(FULL, xl, srcHi);
                nyl = __shfl_sync(FULL, yh, srcLo); nyh = __shfl_sync(FULL, yl, srcHi);
            } else {
                nxl = __shfl_sync(FULL, xl, srcLo); nxh = __shfl_sync(FULL, xh, srcHi);
                nyl = __shfl_sync(FULL, yl, srcLo); nyh = __shfl_sync(FULL, yh, srcHi);
            }
            X[k] = PK(nxl, nxh); Y[k] = PK(nyl, nyh);
        }
        // w9: ctrl lane bit0, tgt pack bit3 -> lane-conditional pack swap
#pragma unroll
        for (int k = 0; k < 8; k++) {
            u64 a = X[k], d = X[k + 8];
            X[k] = c0 ? d : a; X[k + 8] = c0 ? a : d;
            a = Y[k]; d = Y[k + 8];
            Y[k] = c0 ? d : a; Y[k + 8] = c0 ? a : d;
        }
    }

    // ---- readout: sum_i |amp_i|^2 * coef(i), packed ----
    float pw[10];
#pragma unroll
    for (int w = 0; w < 10; w++) pw[w] = post_W[w];

    float laneCoef = 0.f;
#pragma unroll
    for (int w = 5; w < 10; w++)
        laneCoef += ((lane >> (9 - w)) & 1) ? -pw[w] : pw[w];

    u64 acc2 = 0ull;
#pragma unroll
    for (int k = 0; k < 16; k++) {
        float base = laneCoef;
#pragma unroll
        for (int w = 0; w < 4; w++)
            base += ((k >> (3 - w)) & 1) ? -pw[w] : pw[w];
        const u64 cp = PK(base + pw[4], base - pw[4]);
        const u64 p2 = F2(X[k], X[k], M2(Y[k], Y[k]));
        acc2 = F2(p2, cp, acc2);
    }
    float aLo, aHi;
    UPK(acc2, aLo, aHi);
    float acc = aLo + aHi;

#pragma unroll
    for (int off = 16; off; off >>= 1)
        acc += __shfl_xor_sync(FULL, acc, off);

    if (lane == 0)
        out[samp] = readout[0] * (acc + post_b[0]) + bias[0];
}

extern "C" void kernel_launch(void* const* d_in, const int* in_sizes, int n_in,
                              void* d_out, int out_size)
{
    const float* x       = (const float*)d_in[0];
    const float* weights = (const float*)d_in[1];
    const float* post_W  = (const float*)d_in[2];
    const float* post_b  = (const float*)d_in[3];
    const float* readout = (const float*)d_in[4];
    const float* bias    = (const float*)d_in[5];
    float* out = (float*)d_out;

    const int batch = in_sizes[0] / 2;
    prep_kernel<<<1, 64>>>(weights);

    const int threads = 256;
    const int total_threads = batch * 32;
    const int blocks = (total_threads + threads - 1) / threads;
    qsim_kernel<<<blocks, threads>>>(x, post_W, post_b, readout, bias, out, batch);
}

// round 8
// speedup vs baseline: 2.9456x; 1.1452x over previous
#include <cuda_runtime.h>

#define FULL 0xffffffffu

typedef unsigned long long u64;

struct C { float x, y; };

// ---------- f32x2 packed helpers ----------
__device__ __forceinline__ u64 PK(float lo, float hi) {
    u64 r;
    asm("mov.b64 %0, {%1, %2};" : "=l"(r)
        : "r"(__float_as_uint(lo)), "r"(__float_as_uint(hi)));
    return r;
}
__device__ __forceinline__ void UPK(u64 p, float& lo, float& hi) {
    unsigned a, b;
    asm("mov.b64 {%0, %1}, %2;" : "=r"(a), "=r"(b) : "l"(p));
    lo = __uint_as_float(a); hi = __uint_as_float(b);
}
__device__ __forceinline__ u64 F2(u64 a, u64 b, u64 c) {
    u64 d;
    asm("fma.rn.f32x2 %0, %1, %2, %3;" : "=l"(d) : "l"(a), "l"(b), "l"(c));
    return d;
}
__device__ __forceinline__ u64 M2(u64 a, u64 b) {
    u64 d;
    asm("mul.rn.f32x2 %0, %1, %2;" : "=l"(d) : "l"(a), "l"(b));
    return d;
}
__device__ __forceinline__ u64 B2(float v) { return PK(v, v); }
__device__ __forceinline__ u64 SW64(u64 p) { float l, h; UPK(p, l, h); return PK(h, l); }
__device__ __forceinline__ u64 SHX64(u64 p, int m) {
    float l, h; UPK(p, l, h);
    return PK(__shfl_xor_sync(FULL, l, m), __shfl_xor_sync(FULL, h, m));
}
__device__ __forceinline__ C cmul(C a, C b) {
    C r;
    r.x = fmaf(a.x, b.x, -a.y * b.y);
    r.y = fmaf(a.x, b.y,  a.y * b.x);
    return r;
}
// packed state *= scalar complex c
__device__ __forceinline__ void cmulp(u64& X, u64& Y, C c) {
    u64 cx = B2(c.x), cy = B2(c.y), ny = B2(-c.y);
    u64 nX = F2(cx, X, M2(ny, Y));
    u64 nY = F2(cx, Y, M2(cy, X));
    X = nX; Y = nY;
}

// ---------- precomputed Rot matrices (weight-only, grid-uniform) ----------
__device__ float4 g_U[60];  // SU(2) Rot = [[a,b],[-conj(b),conj(a)]] -> {a.x,a.y,b.x,b.y}

__global__ void prep_kernel(const float* __restrict__ weights) {
    int idx = threadIdx.x;
    if (idx >= 60) return;
    float phi = weights[3 * idx + 0];
    float th  = weights[3 * idx + 1];
    float om  = weights[3 * idx + 2];
    float st, ct, sa, ca, sb, cb;
    __sincosf(0.5f * th,         &st, &ct);
    __sincosf(0.5f * (phi + om), &sa, &ca);
    __sincosf(0.5f * (phi - om), &sb, &cb);
    g_U[idx] = make_float4(ca * ct, -sa * ct, -cb * st, -sb * st);
}

// fused gate coefficients: M = Rot * (RY*RX) in SU(2) form {ga, gb}
__device__ __forceinline__ void buildG(float4 u, C ag, C bg, C& ga, C& gb) {
    const C au{u.x, u.y}, bu{u.z, u.w};
    ga.x = fmaf(au.x, ag.x, fmaf(-au.y, ag.y, fmaf(-bu.x, bg.x, -bu.y * bg.y)));
    ga.y = fmaf(au.x, ag.y, fmaf( au.y, ag.x, fmaf(-bu.y, bg.x,  bu.x * bg.y)));
    gb.x = fmaf(au.x, bg.x, fmaf(-au.y, bg.y, fmaf( bu.x, ag.x,  bu.y * ag.y)));
    gb.y = fmaf(au.x, bg.y, fmaf( au.y, bg.x, fmaf( bu.y, ag.x, -bu.x * ag.y)));
}

// ---------- CNOT ring on packed state ----------
__device__ __forceinline__ void ring(u64 (&X)[16], u64 (&Y)[16],
                                     int srcLo, int srcHi, bool c0) {
    // w0..w2: pure pack-index swaps (register renames)
#pragma unroll
    for (int k = 0; k < 16; k++)
        if ((k & 8) && !(k & 4)) { u64 t = X[k]; X[k] = X[k ^ 4]; X[k ^ 4] = t;
                                   t = Y[k]; Y[k] = Y[k ^ 4]; Y[k ^ 4] = t; }
#pragma unroll
    for (int k = 0; k < 16; k++)
        if ((k & 4) && !(k & 2)) { u64 t = X[k]; X[k] = X[k ^ 2]; X[k ^ 2] = t;
                                   t = Y[k]; Y[k] = Y[k ^ 2]; Y[k ^ 2] = t; }
#pragma unroll
    for (int k = 0; k < 16; k++)
        if ((k & 2) && !(k & 1)) { u64 t = X[k]; X[k] = X[k ^ 1]; X[k ^ 1] = t;
                                   t = Y[k]; Y[k] = Y[k ^ 1]; Y[k ^ 1] = t; }
    // w3 (odd packs swap halves) + w4 (hi halves xor16) + w5..w8 (lane perms)
#pragma unroll
    for (int k = 0; k < 16; k++) {
        float xl, xh, yl, yh;
        UPK(X[k], xl, xh); UPK(Y[k], yl, yh);
        float nxl, nxh, nyl, nyh;
        if (k & 1) {
            nxl = __shfl_sync(FULL, xh, srcLo); nxh = __shfl_sync(FULL, xl, srcHi);
            nyl = __shfl_sync(FULL, yh, srcLo); nyh = __shfl_sync(FULL, yl, srcHi);
        } else {
            nxl = __shfl_sync(FULL, xl, srcLo); nxh = __shfl_sync(FULL, xh, srcHi);
            nyl = __shfl_sync(FULL, yl, srcLo); nyh = __shfl_sync(FULL, yh, srcHi);
        }
        X[k] = PK(nxl, nxh); Y[k] = PK(nyl, nyh);
    }
    // w9: ctrl lane bit0, tgt pack bit3 -> lane-conditional pack swap
#pragma unroll
    for (int k = 0; k < 8; k++) {
        u64 a = X[k], d = X[k + 8];
        X[k] = c0 ? d : a; X[k + 8] = c0 ? a : d;
        a = Y[k]; d = Y[k + 8];
        Y[k] = c0 ? d : a; Y[k + 8] = c0 ? a : d;
    }
}

// ===================== main kernel =====================
// amplitude i = r*32 + lane, r = 2k + h.
// X[k] packs {Re(amp[2k]),Re(amp[2k+1])}; Y[k] imag.
// wire w <-> bit 9-w of i: w0..w3 -> pack bits 3..0, w4 -> half h, w5..w9 -> lane bits 4..0.
__global__ void __launch_bounds__(256, 2)
qsim_kernel(const float* __restrict__ x,
            const float* __restrict__ post_W,
            const float* __restrict__ post_b,
            const float* __restrict__ readout,
            const float* __restrict__ bias,
            float* __restrict__ out,
            int batch)
{
    const int lane = threadIdx.x & 31;
    const int samp = (int)((blockIdx.x * blockDim.x + threadIdx.x) >> 5);
    if (samp >= batch) return;

    const float x0 = x[2 * samp + 0];
    const float x1 = x[2 * samp + 1];
    float sx0, cx0, sx1, cx1;
    __sincosf(0.5f * x0, &sx0, &cx0);
    __sincosf(0.5f * x1, &sx1, &cx1);

    const C ag   { cx1 * cx0,  sx1 * sx0 };
    const C bg_e { -sx1 * cx0, -cx1 * sx0 };  // even wires: RX(x0), RY(x1)
    const C bg_o { -sx0 * cx1, -cx0 * sx1 };  // odd  wires: RX(x1), RY(x0)

    // Composed CNOT lane permutation (w5..w8) + w4 half-xor:
    int gsrc = lane;
    gsrc = (gsrc & 2)  ? (gsrc ^ 1) : gsrc;
    gsrc = (gsrc & 4)  ? (gsrc ^ 2) : gsrc;
    gsrc = (gsrc & 8)  ? (gsrc ^ 4) : gsrc;
    gsrc = (gsrc & 16) ? (gsrc ^ 8) : gsrc;
    const int srcLo = gsrc, srcHi = gsrc ^ 16;
    const bool c0 = (lane & 1) != 0;

    u64 X[16], Y[16];

    // ======== layer 0: product state built directly (no butterflies) ========
    {
        // per-wire |0>-columns: f0 = ga, f1 = -conj(gb)
        C f0[10], f1[10];
#pragma unroll
        for (int w = 0; w < 10; w++) {
            C ga, gb;
            buildG(g_U[w], ag, (w & 1) ? bg_o : bg_e, ga, gb);
            f0[w] = ga;
            f1[w] = C{-gb.x, gb.y};
        }
        // lane factor: wires 5..9 selected by lane bits 4..0
        C Lc = ((lane >> 4) & 1) ? f1[5] : f0[5];
        Lc = cmul(Lc, ((lane >> 3) & 1) ? f1[6] : f0[6]);
        Lc = cmul(Lc, ((lane >> 2) & 1) ? f1[7] : f0[7]);
        Lc = cmul(Lc, ((lane >> 1) & 1) ? f1[8] : f0[8]);
        Lc = cmul(Lc, ( lane       & 1) ? f1[9] : f0[9]);
        // half factor (wire 4): pack halves h=0/h=1
        C h0 = cmul(Lc, f0[4]);
        C h1 = cmul(Lc, f1[4]);
        X[0] = PK(h0.x, h1.x);
        Y[0] = PK(h0.y, h1.y);
        // tensor tree over pack bits: bit0=wire3, bit1=wire2, bit2=wire1, bit3=wire0
        X[1] = X[0]; Y[1] = Y[0];
        cmulp(X[0], Y[0], f0[3]); cmulp(X[1], Y[1], f1[3]);
#pragma unroll
        for (int k = 0; k < 2; k++) {
            X[k + 2] = X[k]; Y[k + 2] = Y[k];
            cmulp(X[k], Y[k], f0[2]); cmulp(X[k + 2], Y[k + 2], f1[2]);
        }
#pragma unroll
        for (int k = 0; k < 4; k++) {
            X[k + 4] = X[k]; Y[k + 4] = Y[k];
            cmulp(X[k], Y[k], f0[1]); cmulp(X[k + 4], Y[k + 4], f1[1]);
        }
#pragma unroll
        for (int k = 0; k < 8; k++) {
            X[k + 8] = X[k]; Y[k + 8] = Y[k];
            cmulp(X[k], Y[k], f0[0]); cmulp(X[k + 8], Y[k + 8], f1[0]);
        }
    }
    ring(X, Y, srcLo, srcHi, c0);

    // ======== layers 1..5: full butterflies ========
#pragma unroll 1
    for (int layer = 1; layer < 6; layer++) {
        const float4* Ul = g_U + layer * 10;

#pragma unroll
        for (int w = 0; w < 10; w++) {
            C ga, gb;
            buildG(Ul[w], ag, (w & 1) ? bg_o : bg_e, ga, gb);

            if (w <= 3) {
                const int ks = 8 >> w;
                const u64 paxx = B2(ga.x), pnay = B2(-ga.y), ppay = B2(ga.y);
                const u64 pbxx = B2(gb.x), pnbx = B2(-gb.x);
                const u64 pnby = B2(-gb.y), ppby = B2(gb.y);
#pragma unroll
                for (int kl = 0; kl < 16; kl++) {
                    if (kl & ks) continue;
                    const int kh = kl | ks;
                    u64 Xl = X[kl], Yl = Y[kl], Xh = X[kh], Yh = Y[kh];
                    X[kl] = F2(paxx, Xl, F2(pnay, Yl, F2(pbxx, Xh, M2(pnby, Yh))));
                    Y[kl] = F2(paxx, Yl, F2(ppay, Xl, F2(pbxx, Yh, M2(ppby, Xh))));
                    X[kh] = F2(paxx, Xh, F2(ppay, Yh, F2(pnbx, Xl, M2(pnby, Yl))));
                    Y[kh] = F2(paxx, Yh, F2(pnay, Xh, F2(pnbx, Yl, M2(ppby, Xl))));
                }
            } else if (w == 4) {
                const u64 qaxx = B2(ga.x);
                const u64 qay  = PK(-ga.y,  ga.y);
                const u64 qay2 = PK( ga.y, -ga.y);
                const u64 qbx  = PK( gb.x, -gb.x);
                const u64 qnby = B2(-gb.y), qpby = B2(gb.y);
#pragma unroll
                for (int k = 0; k < 16; k++) {
                    u64 Xs = SW64(X[k]), Ys = SW64(Y[k]);
                    u64 nX = F2(qaxx, X[k], F2(qay,  Y[k], F2(qbx, Xs, M2(qnby, Ys))));
                    u64 nY = F2(qaxx, Y[k], F2(qay2, X[k], F2(qbx, Ys, M2(qpby, Xs))));
                    X[k] = nX; Y[k] = nY;
                }
            } else {
                const int m = 1 << (9 - w);
                const bool hib = (lane & m) != 0;
                const float aly = hib ? -ga.y : ga.y;
                const float bex = hib ? -gb.x : gb.x;
                const u64 pA   = B2(ga.x);
                const u64 pAy  = B2(aly),  pnAy = B2(-aly);
                const u64 pBx  = B2(bex);
                const u64 pBy  = B2(gb.y), pnBy = B2(-gb.y);
#pragma unroll
                for (int k = 0; k < 16; k++) {
                    u64 OX = SHX64(X[k], m), OY = SHX64(Y[k], m);
                    u64 nX = F2(pA, X[k], F2(pnAy, Y[k], F2(pBx, OX, M2(pnBy, OY))));
                    u64 nY = F2(pA, Y[k], F2(pAy,  X[k], F2(pBx, OY, M2(pBy,  OX))));
                    X[k] = nX; Y[k] = nY;
                }
            }
        }

        ring(X, Y, srcLo, srcHi, c0);
    }

    // ---- readout ----
    float pw[10];
#pragma unroll
    for (int w = 0; w < 10; w++) pw[w] = post_W[w];

    float laneCoef = 0.f;
#pragma unroll
    for (int w = 5; w < 10; w++)
        laneCoef += ((lane >> (9 - w)) & 1) ? -pw[w] : pw[w];

    u64 acc2 = 0ull;
#pragma unroll
    for (int k = 0; k < 16; k++) {
        float base = laneCoef;
#pragma unroll
        for (int w = 0; w < 4; w++)
            base += ((k >> (3 - w)) & 1) ? -pw[w] : pw[w];
        const u64 cp = PK(base + pw[4], base - pw[4]);
        const u64 p2 = F2(X[k], X[k], M2(Y[k], Y[k]));
        acc2 = F2(p2, cp, acc2);
    }
    float aLo, aHi;
    UPK(acc2, aLo, aHi);
    float acc = aLo + aHi;

#pragma unroll
    for (int off = 16; off; off >>= 1)
        acc += __shfl_xor_sync(FULL, acc, off);

    if (lane == 0)
        out[samp] = readout[0] * (acc + post_b[0]) + bias[0];
}

extern "C" void kernel_launch(void* const* d_in, const int* in_sizes, int n_in,
                              void* d_out, int out_size)
{
    const float* x       = (const float*)d_in[0];
    const float* weights = (const float*)d_in[1];
    const float* post_W  = (const float*)d_in[2];
    const float* post_b  = (const float*)d_in[3];
    const float* readout = (const float*)d_in[4];
    const float* bias    = (const float*)d_in[5];
    float* out = (float*)d_out;

    const int batch = in_sizes[0] / 2;
    prep_kernel<<<1, 64>>>(weights);

    const int threads = 256;
    const int total_threads = batch * 32;
    const int blocks = (total_threads + threads - 1) / threads;
    qsim_kernel<<<blocks, threads>>>(x, post_W, post_b, readout, bias, out, batch);
}